// round 10
// baseline (speedup 1.0000x reference)
#include <cuda_runtime.h>
#include <cuda_bf16.h>
#include <cstdint>

#define NSEQ 384
#define CIN  128
#define NH   4
#define DH   32
#define NTOK (NSEQ*NSEQ)
#define XS   132   // xn smem stride
#define WS   136   // W smem stride (pair-permuted LDS.64 bank-perfect)
#define LOG2E 1.4426950408889634f

// ---- tf32 helpers ----
__device__ __forceinline__ uint32_t tf32u(float x) {
    uint32_t r; asm("cvt.rna.tf32.f32 %0, %1;" : "=r"(r) : "f"(x)); return r;
}
__device__ __forceinline__ float tf32f(float x) {
    return __uint_as_float(tf32u(x));
}
__device__ __forceinline__ float ex2(float x) {
    float r; asm("ex2.approx.f32 %0, %1;" : "=f"(r) : "f"(x)); return r;
}
__device__ __forceinline__ void mma_tf32(float c[4],
    uint32_t a0, uint32_t a1, uint32_t a2, uint32_t a3,
    uint32_t b0, uint32_t b1)
{
    asm("mma.sync.aligned.m16n8k8.row.col.f32.tf32.tf32.f32 "
        "{%0,%1,%2,%3}, {%4,%5,%6,%7}, {%8,%9}, {%0,%1,%2,%3};"
        : "+f"(c[0]), "+f"(c[1]), "+f"(c[2]), "+f"(c[3])
        : "r"(a0), "r"(a1), "r"(a2), "r"(a3), "r"(b0), "r"(b1));
}
__device__ __forceinline__ uint32_t s2u(const void* p) {
    uint32_t a;
    asm("{ .reg .u64 t; cvta.to.shared.u64 t, %1; cvt.u32.u64 %0, t; }"
        : "=r"(a) : "l"(p));
    return a;
}
__device__ __forceinline__ void cpa16(uint32_t dst, const void* src) {
    asm volatile("cp.async.cg.shared.global [%0], [%1], 16;" :: "r"(dst), "l"(src));
}
#define CPA_COMMIT() asm volatile("cp.async.commit_group;" ::: "memory")
#define CPA_WAIT(n)  asm volatile("cp.async.wait_group %0;" :: "n"(n) : "memory")

// ---- scratch ----
__device__ float g_q  [NSEQ*NH*NSEQ*DH];   // tf32 bits, q pre-scaled by sc*log2e
__device__ float g_k  [NSEQ*NH*NSEQ*DH];   // tf32 bits
__device__ float g_v  [NSEQ*NH*NSEQ*DH];   // tf32 bits
__device__ float g_act[(size_t)NTOK*CIN];
__device__ float g_eb  [NH*NTOK];          // ex2(tri-bias * log2e)  (multiplicative)
__device__ float g_wt [5*CIN*CIN];         // tf32, pair-permuted: wq wk wv wg wo

// ============================================================================
// Kernel 0: one-time weight convert (tf32 + pair permutation)
// ============================================================================
__global__ void k0_prep(const float* __restrict__ wq, const float* __restrict__ wk,
                        const float* __restrict__ wv, const float* __restrict__ wg,
                        const float* __restrict__ wo)
{
    const int idx = blockIdx.x * 256 + threadIdx.x;      // 81920
    const int m   = idx >> 14;
    const int rem = idx & 16383;
    const int o   = rem >> 7, c = rem & 127;
    const float* srcs[5] = {wq, wk, wv, wg, wo};
    const float v = srcs[m][o*CIN + c];
    const int cperm = (c & ~7) | ((c & 4) >> 2) | ((c & 3) << 1);
    g_wt[m*16384 + o*CIN + cperm] = tf32f(v);
}

// ============================================================================
// Kernel 1: LayerNorm + q/k/v/gate projections (tf32 mma) + tri-bias (as ex2).
// ============================================================================
__global__ __launch_bounds__(256, 2) void k1_ln_proj(
    const float* __restrict__ x,   const float* __restrict__ gamma,
    const float* __restrict__ beta,const float* __restrict__ wbias,
    const float* __restrict__ bg)
{
    extern __shared__ float sm[];
    float* xs = sm;                          // [128][XS] — dead after A-frag load
    float* wb[2] = { sm, sm + 64*WS };       // W double buffers (reuse xs space)

    const int tid  = threadIdx.x;
    const int warp = tid >> 5, lane = tid & 31;
    const int gr   = lane >> 2, gc = lane & 3;
    const int t0   = blockIdx.x * 128;

    // ---- LayerNorm -> xs (tf32 rounded) ----
    const float4 gm = *(const float4*)(gamma + lane*4);
    const float4 bt = *(const float4*)(beta  + lane*4);
    for (int kk = 0; kk < 16; kk++) {
        const int lt = warp*16 + kk;
        const float4 xv = *(const float4*)(x + (size_t)(t0+lt)*CIN + lane*4);
        float s = xv.x + xv.y + xv.z + xv.w;
        #pragma unroll
        for (int o = 16; o; o >>= 1) s += __shfl_xor_sync(0xffffffffu, s, o);
        const float mu = s * (1.0f/128.0f);
        const float d0 = xv.x-mu, d1 = xv.y-mu, d2 = xv.z-mu, d3 = xv.w-mu;
        float vs = d0*d0 + d1*d1 + d2*d2 + d3*d3;
        #pragma unroll
        for (int o = 16; o; o >>= 1) vs += __shfl_xor_sync(0xffffffffu, vs, o);
        const float rs = rsqrtf(vs * (1.0f/128.0f) + 1e-5f);
        float4 r4;
        r4.x = tf32f(d0*rs*gm.x + bt.x); r4.y = tf32f(d1*rs*gm.y + bt.y);
        r4.z = tf32f(d2*rs*gm.z + bt.z); r4.w = tf32f(d3*rs*gm.w + bt.w);
        *(float4*)(xs + lt*XS + lane*4) = r4;
    }
    __syncthreads();

    // ---- tri-bias projection -> multiplicative ex2 form ----
    {
        const int lt = tid & 127;
        const int h0 = (tid >> 7) * 2;
        #pragma unroll
        for (int hh = 0; hh < 2; hh++) {
            const int h = h0 + hh;
            float sacc = 0.f;
            #pragma unroll 8
            for (int c0 = 0; c0 < CIN; c0 += 4) {
                const float4 xv = *(const float4*)(xs + lt*XS + c0);
                const float4 wv = *(const float4*)(wbias + h*CIN + c0);
                sacc += xv.x*wv.x + xv.y*wv.y + xv.z*wv.z + xv.w*wv.w;
            }
            g_eb[h*NTOK + t0 + lt] = ex2(sacc * LOG2E);
        }
    }

    // ---- A fragments: warp's 16 tokens x 128 c ----
    const int m0 = warp * 16;
    uint32_t a[16][4];
    #pragma unroll
    for (int ks = 0; ks < 16; ks++) {
        a[ks][0] = __float_as_uint(xs[(m0+gr  )*XS + ks*8 + gc    ]);
        a[ks][1] = __float_as_uint(xs[(m0+gr+8)*XS + ks*8 + gc    ]);
        a[ks][2] = __float_as_uint(xs[(m0+gr  )*XS + ks*8 + gc + 4]);
        a[ks][3] = __float_as_uint(xs[(m0+gr+8)*XS + ks*8 + gc + 4]);
    }
    __syncthreads();     // xs fully consumed; buffers may now overwrite it

    const uint32_t wbu[2] = { s2u(wb[0]), s2u(wb[1]) };

    // prefetch phases 0 and 1
    #pragma unroll
    for (int q = 0; q < 2; q++) {
        const float* src = g_wt + q*8192;
        #pragma unroll
        for (int s = 0; s < 8; s++) {
            const int idx = tid + 256*s;               // 2048 chunks of 16B
            const int o = idx >> 5, c4 = (idx & 31) * 4;
            cpa16(wbu[q] + (o*WS + c4)*4, src + o*CIN + c4);
        }
        CPA_COMMIT();
    }

    const int i_row = t0 / NSEQ;
    const int jb    = t0 % NSEQ;
    const int j0    = jb + m0 + gr;

    for (int p = 0; p < 8; p++) {
        if (p == 7) { CPA_WAIT(0); } else { CPA_WAIT(1); }
        __syncthreads();                      // buf[p&1] ready for all warps

        const float* wS = wb[p & 1];
        float acc[8][4];
        #pragma unroll
        for (int nt = 0; nt < 8; nt++)
            #pragma unroll
            for (int e = 0; e < 4; e++) acc[nt][e] = 0.f;

        #pragma unroll
        for (int ks = 0; ks < 16; ks++) {
            #pragma unroll
            for (int nt = 0; nt < 8; nt++) {
                const float2 b = *(const float2*)(wS + (nt*8+gr)*WS + ks*8 + 2*gc);
                mma_tf32(acc[nt], a[ks][0], a[ks][1], a[ks][2], a[ks][3],
                         __float_as_uint(b.x), __float_as_uint(b.y));
            }
        }
        __syncthreads();                      // all warps done reading buf[p&1]

        if (p + 2 < 8) {                      // prefetch phase p+2 into buf[p&1]
            const float* src = g_wt + (p+2)*8192;
            #pragma unroll
            for (int s = 0; s < 8; s++) {
                const int idx = tid + 256*s;
                const int o = idx >> 5, c4 = (idx & 31) * 4;
                cpa16(wbu[p & 1] + (o*WS + c4)*4, src + o*CIN + c4);
            }
            CPA_COMMIT();
        }

        // ---- epilogue (overlaps with async copies) ----
        const int grp = p >> 1;
        const int ob  = (p & 1) * 64;
        if (grp < 3) {
            float* dst = (grp==0) ? g_q : (grp==1) ? g_k : g_v;
            const float sc = (grp==0) ? 0.17677669529663687f * LOG2E : 1.0f;
            #pragma unroll
            for (int nt = 0; nt < 8; nt++) {
                const int o = ob + nt*8 + 2*gc;
                const int h = o >> 5, d = o & 31;
                float* ptr = dst + ((size_t)(i_row*NH + h)*NSEQ + j0)*DH + d;
                *(float2*)ptr = make_float2(tf32f(acc[nt][0]*sc), tf32f(acc[nt][1]*sc));
                *(float2*)(ptr + 8*DH) =
                    make_float2(tf32f(acc[nt][2]*sc), tf32f(acc[nt][3]*sc));
            }
        } else {
            const int tok = t0 + m0 + gr;
            #pragma unroll
            for (int nt = 0; nt < 8; nt++) {
                const int o = ob + nt*8 + 2*gc;
                const float2 bgv = __ldg((const float2*)(bg + o));
                float2 lo, hi;
                lo.x = 1.0f/(1.0f+__expf(-(acc[nt][0]+bgv.x)));
                lo.y = 1.0f/(1.0f+__expf(-(acc[nt][1]+bgv.y)));
                hi.x = 1.0f/(1.0f+__expf(-(acc[nt][2]+bgv.x)));
                hi.y = 1.0f/(1.0f+__expf(-(acc[nt][3]+bgv.y)));
                *(float2*)(g_act + (size_t)tok*CIN + o)     = lo;
                *(float2*)(g_act + (size_t)(tok+8)*CIN + o) = hi;
            }
        }
    }
}

// ============================================================================
// Kernel 2: flash attention per (i,h), tf32 mma.
// 384 threads (12 warps, 6/SMSP at occ 2). V stored K-layout with dim scatter
// p(d)=4(d>>3)+(d&3)+((d&4)<<2)  -> AV B-frag scalar LDS hit all 32 banks.
// No V transpose: K and V both filled near-raw. Multiplicative bias.
// ============================================================================
#define KST 36

__global__ __launch_bounds__(384, 2) void k2_attn(const float* __restrict__ mask)
{
    extern __shared__ float sm[];
    float* Ksm = sm;                       // [384][36]  raw [key][dim]
    float* Vsm = sm + NSEQ*KST;            // [384][36]  [key][p(dim)]
    float* msm = Vsm + NSEQ*KST;           // [384]      multiplicative mask

    const int tid  = threadIdx.x;
    const int warp = tid >> 5, lane = tid & 31;
    const int gr   = lane >> 2, gc = lane & 3;
    const int src0 = (lane & ~3) | ((lane & 3) >> 1);
    const int src1 = src0 + 2;
    const bool sel = (lane & 1);
    const int vbase = (gr & 3) + ((gr >> 2) << 4);   // f(gr) for scattered V dims
    const int i = blockIdx.x >> 2;
    const int h = blockIdx.x & 3;
    const int base = ((i*NH) + h) * NSEQ * DH;

    // K: raw async copy
    {
        const uint32_t ku = s2u(Ksm);
        #pragma unroll
        for (int it = 0; it < 8; it++) {
            const int idx = tid + 384*it;          // 3072 chunks
            const int j = idx >> 3, cq = (idx & 7) * 4;
            cpa16(ku + (j*KST + cq)*4, g_k + base + j*DH + cq);
        }
        CPA_COMMIT();
    }
    // V: [key][p(dim)] scatter (float4-preserving: p is contiguous on 4-groups)
    #pragma unroll
    for (int it = 0; it < 8; it++) {
        const int idx = tid + 384*it;
        const int j = idx >> 3, dq = (idx & 7) * 4;
        const float4 vv = *(const float4*)(g_v + base + j*DH + dq);
        const int pp = 4*(dq >> 3) + ((dq & 4) << 2);
        *(float4*)(Vsm + j*KST + pp) = vv;
    }
    if (tid < NSEQ)
        msm[tid] = ex2((mask[i*NSEQ + tid] - 1.0f) * (1e9f * LOG2E));
    CPA_WAIT(0);
    __syncthreads();

    const float* __restrict__ tb = g_eb + h*NTOK;

    for (int t = 0; t < 2; t++) {
        const int jq0 = (warp + 12*t) * 16;

        uint32_t qa[4][4];
        const float* Qp  = g_q + base + (jq0+gr)*DH;
        const float* Qp8 = Qp + 8*DH;
        #pragma unroll
        for (int ks = 0; ks < 4; ks++) {
            qa[ks][0] = __float_as_uint(__ldg(&Qp [8*ks + gc]));
            qa[ks][1] = __float_as_uint(__ldg(&Qp8[8*ks + gc]));
            qa[ks][2] = __float_as_uint(__ldg(&Qp [8*ks + gc + 4]));
            qa[ks][3] = __float_as_uint(__ldg(&Qp8[8*ks + gc + 4]));
        }

        float s0 = 0.f, s1 = 0.f;
        float o[4][4];
        #pragma unroll
        for (int j = 0; j < 4; j++)
            #pragma unroll
            for (int e = 0; e < 4; e++) o[j][e] = 0.f;

        const float* tbr0 = tb + (size_t)(jq0+gr)*NSEQ;
        const float* tbr1 = tbr0 + 8*NSEQ;

        for (int n0 = 0; n0 < NSEQ; n0 += 32) {
            // ---- QK MMA ----
            float c[4][4];
            #pragma unroll
            for (int j = 0; j < 4; j++) {
                #pragma unroll
                for (int e = 0; e < 4; e++) c[j][e] = 0.f;
                const float* kb = Ksm + (n0 + 8*j + gr)*KST;
                #pragma unroll
                for (int ks = 0; ks < 4; ks++) {
                    const uint32_t b0 = __float_as_uint(kb[8*ks + gc]);
                    const uint32_t b1 = __float_as_uint(kb[8*ks + gc + 4]);
                    mma_tf32(c[j], qa[ks][0], qa[ks][1], qa[ks][2], qa[ks][3], b0, b1);
                }
            }

            // ---- p = ex2(qk) * eb * mask ----
            #pragma unroll
            for (int j = 0; j < 4; j++) {
                const float2 e0 = __ldg((const float2*)(tbr0 + n0 + 8*j + 2*gc));
                const float2 e1 = __ldg((const float2*)(tbr1 + n0 + 8*j + 2*gc));
                const float2 mk = *(const float2*)(msm + n0 + 8*j + 2*gc);
                const float p0 = ex2(c[j][0]) * (e0.x*mk.x);
                const float p1 = ex2(c[j][1]) * (e0.y*mk.y);
                const float p2 = ex2(c[j][2]) * (e1.x*mk.x);
                const float p3 = ex2(c[j][3]) * (e1.y*mk.y);
                s0 += p0 + p1; s1 += p2 + p3;
                c[j][0] = p0; c[j][1] = p1;
                c[j][2] = p2; c[j][3] = p3;
            }

            // ---- AV: shuffle refragment; B-frags direct from scattered Vsm ----
            #pragma unroll
            for (int ks = 0; ks < 4; ks++) {
                const float x0 = __shfl_sync(0xffffffffu, c[ks][0], src0);
                const float x1 = __shfl_sync(0xffffffffu, c[ks][1], src0);
                const float x2 = __shfl_sync(0xffffffffu, c[ks][2], src0);
                const float x3 = __shfl_sync(0xffffffffu, c[ks][3], src0);
                const float y0 = __shfl_sync(0xffffffffu, c[ks][0], src1);
                const float y1 = __shfl_sync(0xffffffffu, c[ks][1], src1);
                const float y2 = __shfl_sync(0xffffffffu, c[ks][2], src1);
                const float y3 = __shfl_sync(0xffffffffu, c[ks][3], src1);
                const uint32_t a0 = __float_as_uint(sel ? x1 : x0);
                const uint32_t a1 = __float_as_uint(sel ? x3 : x2);
                const uint32_t a2 = __float_as_uint(sel ? y1 : y0);
                const uint32_t a3 = __float_as_uint(sel ? y3 : y2);
                const float* vr0 = Vsm + (n0 + 8*ks + gc)*KST + vbase;
                const float* vr1 = vr0 + 4*KST;
                #pragma unroll
                for (int j = 0; j < 4; j++) {
                    const uint32_t b0 = __float_as_uint(vr0[4*j]);
                    const uint32_t b1 = __float_as_uint(vr1[4*j]);
                    mma_tf32(o[j], a0, a1, a2, a3, b0, b1);
                }
            }
        }

        s0 += __shfl_xor_sync(0xffffffffu, s0, 1);
        s0 += __shfl_xor_sync(0xffffffffu, s0, 2);
        s1 += __shfl_xor_sync(0xffffffffu, s1, 1);
        s1 += __shfl_xor_sync(0xffffffffu, s1, 2);
        const float inv0 = 1.0f / s0, inv1 = 1.0f / s1;

        #pragma unroll
        for (int j = 0; j < 4; j++) {
            const int col = h*DH + 8*j + 2*gc;
            const size_t r0 = (size_t)(i*NSEQ + jq0 + gr)*CIN + col;
            const size_t r1 = (size_t)(i*NSEQ + jq0 + gr + 8)*CIN + col;
            const float2 g0 = *(const float2*)(g_act + r0);
            const float2 g1 = *(const float2*)(g_act + r1);
            *(float2*)(g_act + r0) = make_float2(o[j][0]*inv0*g0.x, o[j][1]*inv0*g0.y);
            *(float2*)(g_act + r1) = make_float2(o[j][2]*inv1*g1.x, o[j][3]*inv1*g1.y);
        }
    }
}

// ============================================================================
// Kernel 3: out = act @ wo^T + bo  (tf32 mma, cp.async staged wo)
// ============================================================================
__global__ __launch_bounds__(256, 2) void k3_out(
    const float* __restrict__ bo, float* __restrict__ out)
{
    extern __shared__ float sm[];
    float* xs = sm;                         // [128][XS] — dead after A-frags
    float* wb[2] = { sm, sm + 64*WS };

    const int tid  = threadIdx.x;
    const int warp = tid >> 5, lane = tid & 31;
    const int gr   = lane >> 2, gc = lane & 3;
    const int t0   = blockIdx.x * 128;

    #pragma unroll
    for (int s = 0; s < 16; s++) {
        const int idx = tid + 256*s;
        const int lt = idx >> 5, c0 = (idx & 31) * 4;
        float4 a4 = *(const float4*)(g_act + (size_t)(t0+lt)*CIN + c0);
        a4.x = tf32f(a4.x); a4.y = tf32f(a4.y);
        a4.z = tf32f(a4.z); a4.w = tf32f(a4.w);
        *(float4*)(xs + lt*XS + c0) = a4;
    }
    __syncthreads();

    const int m0 = warp * 16;
    uint32_t a[16][4];
    #pragma unroll
    for (int ks = 0; ks < 16; ks++) {
        a[ks][0] = __float_as_uint(xs[(m0+gr  )*XS + ks*8 + gc    ]);
        a[ks][1] = __float_as_uint(xs[(m0+gr+8)*XS + ks*8 + gc    ]);
        a[ks][2] = __float_as_uint(xs[(m0+gr  )*XS + ks*8 + gc + 4]);
        a[ks][3] = __float_as_uint(xs[(m0+gr+8)*XS + ks*8 + gc + 4]);
    }
    __syncthreads();     // xs consumed

    const uint32_t wbu[2] = { s2u(wb[0]), s2u(wb[1]) };
    #pragma unroll
    for (int q = 0; q < 2; q++) {
        const float* src = g_wt + 4*16384 + q*8192;
        #pragma unroll
        for (int s = 0; s < 8; s++) {
            const int idx = tid + 256*s;
            const int o = idx >> 5, c4 = (idx & 31) * 4;
            cpa16(wbu[q] + (o*WS + c4)*4, src + o*CIN + c4);
        }
        CPA_COMMIT();
    }

    const int tok = t0 + m0 + gr;
    for (int hf = 0; hf < 2; hf++) {
        if (hf == 0) { CPA_WAIT(1); } else { CPA_WAIT(0); }
        __syncthreads();

        const float* wS = wb[hf];
        float acc[8][4];
        #pragma unroll
        for (int nt = 0; nt < 8; nt++)
            #pragma unroll
            for (int e = 0; e < 4; e++) acc[nt][e] = 0.f;

        #pragma unroll
        for (int ks = 0; ks < 16; ks++) {
            #pragma unroll
            for (int nt = 0; nt < 8; nt++) {
                const float2 b = *(const float2*)(wS + (nt*8+gr)*WS + ks*8 + 2*gc);
                mma_tf32(acc[nt], a[ks][0], a[ks][1], a[ks][2], a[ks][3],
                         __float_as_uint(b.x), __float_as_uint(b.y));
            }
        }

        #pragma unroll
        for (int nt = 0; nt < 8; nt++) {
            const int o = hf*64 + nt*8 + 2*gc;
            const float2 bov = __ldg((const float2*)(bo + o));
            *(float2*)(out + (size_t)tok*CIN + o) =
                make_float2(acc[nt][0]+bov.x, acc[nt][1]+bov.y);
            *(float2*)(out + (size_t)(tok+8)*CIN + o) =
                make_float2(acc[nt][2]+bov.x, acc[nt][3]+bov.y);
        }
    }
}

// ============================================================================
extern "C" void kernel_launch(void* const* d_in, const int* in_sizes, int n_in,
                              void* d_out, int out_size)
{
    const float* x     = (const float*)d_in[0];
    const float* mask  = (const float*)d_in[1];
    const float* gamma = (const float*)d_in[2];
    const float* beta  = (const float*)d_in[3];
    const float* wbias = (const float*)d_in[4];
    const float* wq    = (const float*)d_in[5];
    const float* wk    = (const float*)d_in[6];
    const float* wv    = (const float*)d_in[7];
    const float* wg    = (const float*)d_in[8];
    const float* bg    = (const float*)d_in[9];
    const float* wo    = (const float*)d_in[10];
    const float* bo    = (const float*)d_in[11];
    float* out = (float*)d_out;

    const int smem_gemm = 2 * 64 * WS * 4;                    // 69,632 B
    const int smem_attn = (NSEQ*KST*2 + NSEQ) * 4;            // 112,128 B

    cudaFuncSetAttribute(k1_ln_proj, cudaFuncAttributeMaxDynamicSharedMemorySize, smem_gemm);
    cudaFuncSetAttribute(k2_attn,   cudaFuncAttributeMaxDynamicSharedMemorySize, smem_attn);
    cudaFuncSetAttribute(k3_out,    cudaFuncAttributeMaxDynamicSharedMemorySize, smem_gemm);

    k0_prep  <<<320, 256>>>(wq, wk, wv, wg, wo);
    k1_ln_proj<<<NTOK/128, 256, smem_gemm>>>(x, gamma, beta, wbias, bg);
    k2_attn  <<<NSEQ*NH,  384, smem_attn>>>(mask);
    k3_out   <<<NTOK/128, 256, smem_gemm>>>(bo, out);
}

// round 12
// speedup vs baseline: 1.0882x; 1.0882x over previous
#include <cuda_runtime.h>
#include <cuda_bf16.h>
#include <cuda_fp16.h>
#include <cstdint>

#define NSEQ 384
#define CIN  128
#define NH   4
#define DH   32
#define NTOK (NSEQ*NSEQ)
#define LOG2E 1.4426950408889634f

// fp16 smem geometry (bytes): A rows 272 (frag b32 loads bank-perfect),
// W rows 288 (÷4 ≡ 8 mod 32 -> LDS.64 frag loads bank-perfect)
#define XSB 272
#define WSB 288

// ---- helpers ----
__device__ __forceinline__ uint32_t tf32u(float x) {
    uint32_t r; asm("cvt.rna.tf32.f32 %0, %1;" : "=r"(r) : "f"(x)); return r;
}
__device__ __forceinline__ float tf32f(float x) { return __uint_as_float(tf32u(x)); }
__device__ __forceinline__ float ex2(float x) {
    float r; asm("ex2.approx.f32 %0, %1;" : "=f"(r) : "f"(x)); return r;
}
__device__ __forceinline__ void mma_tf32(float c[4],
    uint32_t a0, uint32_t a1, uint32_t a2, uint32_t a3, uint32_t b0, uint32_t b1)
{
    asm("mma.sync.aligned.m16n8k8.row.col.f32.tf32.tf32.f32 "
        "{%0,%1,%2,%3}, {%4,%5,%6,%7}, {%8,%9}, {%0,%1,%2,%3};"
        : "+f"(c[0]), "+f"(c[1]), "+f"(c[2]), "+f"(c[3])
        : "r"(a0), "r"(a1), "r"(a2), "r"(a3), "r"(b0), "r"(b1));
}
__device__ __forceinline__ void mma_f16(float c[4],
    uint32_t a0, uint32_t a1, uint32_t a2, uint32_t a3, uint32_t b0, uint32_t b1)
{
    asm("mma.sync.aligned.m16n8k16.row.col.f32.f16.f16.f32 "
        "{%0,%1,%2,%3}, {%4,%5,%6,%7}, {%8,%9}, {%0,%1,%2,%3};"
        : "+f"(c[0]), "+f"(c[1]), "+f"(c[2]), "+f"(c[3])
        : "r"(a0), "r"(a1), "r"(a2), "r"(a3), "r"(b0), "r"(b1));
}
__device__ __forceinline__ uint32_t s2u(const void* p) {
    uint32_t a;
    asm("{ .reg .u64 t; cvta.to.shared.u64 t, %1; cvt.u32.u64 %0, t; }" : "=r"(a) : "l"(p));
    return a;
}
__device__ __forceinline__ void cpa16(uint32_t dst, const void* src) {
    asm volatile("cp.async.cg.shared.global [%0], [%1], 16;" :: "r"(dst), "l"(src));
}
#define CPA_COMMIT() asm volatile("cp.async.commit_group;" ::: "memory")
#define CPA_WAIT(n)  asm volatile("cp.async.wait_group %0;" :: "n"(n) : "memory")

// ---- scratch ----
__device__ float g_q  [NSEQ*NH*NSEQ*DH];   // fp32 (tf32 bits), q pre-scaled by sc*log2e
__device__ float g_k  [NSEQ*NH*NSEQ*DH];
__device__ float g_v  [NSEQ*NH*NSEQ*DH];
__device__ float g_act[(size_t)NTOK*CIN];
__device__ float g_eb [NH*NTOK];           // ex2(tri-bias * log2e)
__device__ __align__(16) __half g_wh[5*CIN*CIN];  // fp16, k-pair permuted: wq wk wv wg wo

// ============================================================================
// Kernel 0: weights -> fp16, k-pair permuted: within each 16-half k-block,
// pair j (k = 2j,2j+1) goes to slot 2(j&3)+(j>>2), so the m16n8k16 B fragment
// (b0 = k{2gc,2gc+1}, b1 = k{2gc+8,2gc+9}) is one contiguous 8-byte load.
// ============================================================================
__global__ void k0_prep(const float* __restrict__ wq, const float* __restrict__ wk,
                        const float* __restrict__ wv, const float* __restrict__ wg,
                        const float* __restrict__ wo)
{
    const int idx = blockIdx.x * 256 + threadIdx.x;      // 81920
    const int m   = idx >> 14;
    const int rem = idx & 16383;
    const int o   = rem >> 7, c = rem & 127;
    const float* srcs[5] = {wq, wk, wv, wg, wo};
    const float v = srcs[m][o*CIN + c];
    const int j    = (c >> 1) & 7;
    const int slot = 2*(j & 3) + (j >> 2);
    const int cperm = (c & ~15) | (slot << 1) | (c & 1);
    g_wh[m*16384 + o*128 + cperm] = __float2half_rn(v);
}

// ============================================================================
// Kernel 1: LayerNorm + q/k/v/gate projections (fp16 m16n8k16 mma) + tri-bias.
// xn fp16 in smem; W halves (64 outs) cp.async double-buffered, reusing xs.
// 8 phases (4 groups x 2 halves); epilogue identical to tf32 version.
// ============================================================================
__global__ __launch_bounds__(256, 2) void k1_ln_proj(
    const float* __restrict__ x,   const float* __restrict__ gamma,
    const float* __restrict__ beta,const float* __restrict__ wbias,
    const float* __restrict__ bg)
{
    extern __shared__ char smc[];
    __half* xs = (__half*)smc;                 // [128 rows][XSB bytes] — dies after frag load
    char* wb[2] = { smc, smc + 64*WSB };       // W double buffers

    const int tid  = threadIdx.x;
    const int warp = tid >> 5, lane = tid & 31;
    const int gr   = lane >> 2, gc = lane & 3;
    const int t0   = blockIdx.x * 128;

    // ---- LayerNorm -> xs (fp16) ----
    const float4 gm = *(const float4*)(gamma + lane*4);
    const float4 bt = *(const float4*)(beta  + lane*4);
    for (int kk = 0; kk < 16; kk++) {
        const int lt = warp*16 + kk;
        const float4 xv = *(const float4*)(x + (size_t)(t0+lt)*CIN + lane*4);
        float s = xv.x + xv.y + xv.z + xv.w;
        #pragma unroll
        for (int o = 16; o; o >>= 1) s += __shfl_xor_sync(0xffffffffu, s, o);
        const float mu = s * (1.0f/128.0f);
        const float d0 = xv.x-mu, d1 = xv.y-mu, d2 = xv.z-mu, d3 = xv.w-mu;
        float vs = d0*d0 + d1*d1 + d2*d2 + d3*d3;
        #pragma unroll
        for (int o = 16; o; o >>= 1) vs += __shfl_xor_sync(0xffffffffu, vs, o);
        const float rs = rsqrtf(vs * (1.0f/128.0f) + 1e-5f);
        const __half2 h01 = __floats2half2_rn(d0*rs*gm.x + bt.x, d1*rs*gm.y + bt.y);
        const __half2 h23 = __floats2half2_rn(d2*rs*gm.z + bt.z, d3*rs*gm.w + bt.w);
        char* dst = smc + lt*XSB + lane*8;
        *(__half2*)(dst)     = h01;
        *(__half2*)(dst + 4) = h23;
    }
    __syncthreads();

    // ---- tri-bias projection (from fp16 xn) -> multiplicative ex2 form ----
    {
        const int lt = tid & 127;
        const int h0 = (tid >> 7) * 2;
        #pragma unroll
        for (int hh = 0; hh < 2; hh++) {
            const int h = h0 + hh;
            float sacc = 0.f;
            #pragma unroll 8
            for (int c0 = 0; c0 < CIN; c0 += 2) {
                const float2 xf = __half22float2(*(const __half2*)(smc + lt*XSB + c0*2));
                const float2 wv = *(const float2*)(wbias + h*CIN + c0);
                sacc += xf.x*wv.x + xf.y*wv.y;
            }
            g_eb[h*NTOK + t0 + lt] = ex2(sacc * LOG2E);
        }
    }

    // ---- A fragments: warp's 16 tokens x 128 c (8 k-steps of 16) ----
    const int m0 = warp * 16;
    uint32_t a[8][4];
    #pragma unroll
    for (int ks = 0; ks < 8; ks++) {
        const char* rp = smc + (m0+gr)*XSB + ks*32 + gc*4;
        a[ks][0] = *(const uint32_t*)(rp);
        a[ks][1] = *(const uint32_t*)(rp + 8*XSB);
        a[ks][2] = *(const uint32_t*)(rp + 16);
        a[ks][3] = *(const uint32_t*)(rp + 8*XSB + 16);
    }
    __syncthreads();     // xs consumed; W buffers may overwrite

    const uint32_t wbu[2] = { s2u(wb[0]), s2u(wb[1]) };

    // prefetch W phases 0,1 (64 rows x 256B each)
    #pragma unroll
    for (int q = 0; q < 2; q++) {
        const __half* src = g_wh + q*8192;
        #pragma unroll
        for (int s = 0; s < 4; s++) {
            const int idx = tid + 256*s;          // 1024 chunks of 16B
            const int o = idx >> 4, ch = idx & 15;
            cpa16(wbu[q] + o*WSB + ch*16, src + o*128 + ch*8);
        }
        CPA_COMMIT();
    }

    const int i_row = t0 / NSEQ;
    const int jb    = t0 % NSEQ;
    const int j0    = jb + m0 + gr;

    for (int p = 0; p < 8; p++) {
        if (p == 7) { CPA_WAIT(0); } else { CPA_WAIT(1); }
        __syncthreads();

        const char* wS = wb[p & 1];
        float acc[8][4];
        #pragma unroll
        for (int nt = 0; nt < 8; nt++)
            #pragma unroll
            for (int e = 0; e < 4; e++) acc[nt][e] = 0.f;

        #pragma unroll
        for (int ks = 0; ks < 8; ks++) {
            #pragma unroll
            for (int nt = 0; nt < 8; nt++) {
                const uint2 b = *(const uint2*)(wS + (nt*8+gr)*WSB + ks*32 + gc*8);
                mma_f16(acc[nt], a[ks][0], a[ks][1], a[ks][2], a[ks][3], b.x, b.y);
            }
        }
        __syncthreads();

        if (p + 2 < 8) {
            const __half* src = g_wh + (p+2)*8192;
            #pragma unroll
            for (int s = 0; s < 4; s++) {
                const int idx = tid + 256*s;
                const int o = idx >> 4, ch = idx & 15;
                cpa16(wbu[p & 1] + o*WSB + ch*16, src + o*128 + ch*8);
            }
            CPA_COMMIT();
        }

        // ---- epilogue ----
        const int grp = p >> 1;
        const int ob  = (p & 1) * 64;
        if (grp < 3) {
            float* dst = (grp==0) ? g_q : (grp==1) ? g_k : g_v;
            const float sc = (grp==0) ? 0.17677669529663687f * LOG2E : 1.0f;
            #pragma unroll
            for (int nt = 0; nt < 8; nt++) {
                const int o = ob + nt*8 + 2*gc;
                const int h = o >> 5, d = o & 31;
                float* ptr = dst + ((size_t)(i_row*NH + h)*NSEQ + j0)*DH + d;
                *(float2*)ptr = make_float2(tf32f(acc[nt][0]*sc), tf32f(acc[nt][1]*sc));
                *(float2*)(ptr + 8*DH) =
                    make_float2(tf32f(acc[nt][2]*sc), tf32f(acc[nt][3]*sc));
            }
        } else {
            const int tok = t0 + m0 + gr;
            #pragma unroll
            for (int nt = 0; nt < 8; nt++) {
                const int o = ob + nt*8 + 2*gc;
                const float2 bgv = __ldg((const float2*)(bg + o));
                float2 lo, hi;
                lo.x = 1.0f/(1.0f+__expf(-(acc[nt][0]+bgv.x)));
                lo.y = 1.0f/(1.0f+__expf(-(acc[nt][1]+bgv.y)));
                hi.x = 1.0f/(1.0f+__expf(-(acc[nt][2]+bgv.x)));
                hi.y = 1.0f/(1.0f+__expf(-(acc[nt][3]+bgv.y)));
                *(float2*)(g_act + (size_t)tok*CIN + o)     = lo;
                *(float2*)(g_act + (size_t)(tok+8)*CIN + o) = hi;
            }
        }
    }
}

// ============================================================================
// Kernel 2: flash attention per (i,h), tf32 mma.sync (unchanged R8).
// ============================================================================
#define KST 36

__global__ __launch_bounds__(384, 2) void k2_attn(const float* __restrict__ mask)
{
    extern __shared__ float sm[];
    float* Ksm = sm;
    float* Vsm = sm + NSEQ*KST;
    float* msm = Vsm + NSEQ*KST;

    const int tid  = threadIdx.x;
    const int warp = tid >> 5, lane = tid & 31;
    const int gr   = lane >> 2, gc = lane & 3;
    const int src0 = (lane & ~3) | ((lane & 3) >> 1);
    const int src1 = src0 + 2;
    const bool sel = (lane & 1);
    const int vbase = (gr & 3) + ((gr >> 2) << 4);
    const int i = blockIdx.x >> 2;
    const int h = blockIdx.x & 3;
    const int base = ((i*NH) + h) * NSEQ * DH;

    {
        const uint32_t ku = s2u(Ksm);
        #pragma unroll
        for (int it = 0; it < 8; it++) {
            const int idx = tid + 384*it;
            const int j = idx >> 3, cq = (idx & 7) * 4;
            cpa16(ku + (j*KST + cq)*4, g_k + base + j*DH + cq);
        }
        CPA_COMMIT();
    }
    #pragma unroll
    for (int it = 0; it < 8; it++) {
        const int idx = tid + 384*it;
        const int j = idx >> 3, dq = (idx & 7) * 4;
        const float4 vv = *(const float4*)(g_v + base + j*DH + dq);
        const int pp = 4*(dq >> 3) + ((dq & 4) << 2);
        *(float4*)(Vsm + j*KST + pp) = vv;
    }
    if (tid < NSEQ)
        msm[tid] = ex2((mask[i*NSEQ + tid] - 1.0f) * (1e9f * LOG2E));
    CPA_WAIT(0);
    __syncthreads();

    const float* __restrict__ tb = g_eb + h*NTOK;

    for (int t = 0; t < 2; t++) {
        const int jq0 = (warp + 12*t) * 16;

        uint32_t qa[4][4];
        const float* Qp  = g_q + base + (jq0+gr)*DH;
        const float* Qp8 = Qp + 8*DH;
        #pragma unroll
        for (int ks = 0; ks < 4; ks++) {
            qa[ks][0] = __float_as_uint(__ldg(&Qp [8*ks + gc]));
            qa[ks][1] = __float_as_uint(__ldg(&Qp8[8*ks + gc]));
            qa[ks][2] = __float_as_uint(__ldg(&Qp [8*ks + gc + 4]));
            qa[ks][3] = __float_as_uint(__ldg(&Qp8[8*ks + gc + 4]));
        }

        float s0 = 0.f, s1 = 0.f;
        float o[4][4];
        #pragma unroll
        for (int j = 0; j < 4; j++)
            #pragma unroll
            for (int e = 0; e < 4; e++) o[j][e] = 0.f;

        const float* tbr0 = tb + (size_t)(jq0+gr)*NSEQ;
        const float* tbr1 = tbr0 + 8*NSEQ;

        for (int n0 = 0; n0 < NSEQ; n0 += 32) {
            float c[4][4];
            #pragma unroll
            for (int j = 0; j < 4; j++) {
                #pragma unroll
                for (int e = 0; e < 4; e++) c[j][e] = 0.f;
                const float* kb = Ksm + (n0 + 8*j + gr)*KST;
                #pragma unroll
                for (int ks = 0; ks < 4; ks++) {
                    const uint32_t b0 = __float_as_uint(kb[8*ks + gc]);
                    const uint32_t b1 = __float_as_uint(kb[8*ks + gc + 4]);
                    mma_tf32(c[j], qa[ks][0], qa[ks][1], qa[ks][2], qa[ks][3], b0, b1);
                }
            }
            #pragma unroll
            for (int j = 0; j < 4; j++) {
                const float2 e0 = __ldg((const float2*)(tbr0 + n0 + 8*j + 2*gc));
                const float2 e1 = __ldg((const float2*)(tbr1 + n0 + 8*j + 2*gc));
                const float2 mk = *(const float2*)(msm + n0 + 8*j + 2*gc);
                const float p0 = ex2(c[j][0]) * (e0.x*mk.x);
                const float p1 = ex2(c[j][1]) * (e0.y*mk.y);
                const float p2 = ex2(c[j][2]) * (e1.x*mk.x);
                const float p3 = ex2(c[j][3]) * (e1.y*mk.y);
                s0 += p0 + p1; s1 += p2 + p3;
                c[j][0] = p0; c[j][1] = p1; c[j][2] = p2; c[j][3] = p3;
            }
            #pragma unroll
            for (int ks = 0; ks < 4; ks++) {
                const float x0 = __shfl_sync(0xffffffffu, c[ks][0], src0);
                const float x1 = __shfl_sync(0xffffffffu, c[ks][1], src0);
                const float x2 = __shfl_sync(0xffffffffu, c[ks][2], src0);
                const float x3 = __shfl_sync(0xffffffffu, c[ks][3], src0);
                const float y0 = __shfl_sync(0xffffffffu, c[ks][0], src1);
                const float y1 = __shfl_sync(0xffffffffu, c[ks][1], src1);
                const float y2 = __shfl_sync(0xffffffffu, c[ks][2], src1);
                const float y3 = __shfl_sync(0xffffffffu, c[ks][3], src1);
                const uint32_t a0 = __float_as_uint(sel ? x1 : x0);
                const uint32_t a1 = __float_as_uint(sel ? x3 : x2);
                const uint32_t a2 = __float_as_uint(sel ? y1 : y0);
                const uint32_t a3 = __float_as_uint(sel ? y3 : y2);
                const float* vr0 = Vsm + (n0 + 8*ks + gc)*KST + vbase;
                const float* vr1 = vr0 + 4*KST;
                #pragma unroll
                for (int j = 0; j < 4; j++) {
                    const uint32_t b0 = __float_as_uint(vr0[4*j]);
                    const uint32_t b1 = __float_as_uint(vr1[4*j]);
                    mma_tf32(o[j], a0, a1, a2, a3, b0, b1);
                }
            }
        }

        s0 += __shfl_xor_sync(0xffffffffu, s0, 1);
        s0 += __shfl_xor_sync(0xffffffffu, s0, 2);
        s1 += __shfl_xor_sync(0xffffffffu, s1, 1);
        s1 += __shfl_xor_sync(0xffffffffu, s1, 2);
        const float inv0 = 1.0f / s0, inv1 = 1.0f / s1;

        #pragma unroll
        for (int j = 0; j < 4; j++) {
            const int col = h*DH + 8*j + 2*gc;
            const size_t r0 = (size_t)(i*NSEQ + jq0 + gr)*CIN + col;
            const size_t r1 = (size_t)(i*NSEQ + jq0 + gr + 8)*CIN + col;
            const float2 g0 = *(const float2*)(g_act + r0);
            const float2 g1 = *(const float2*)(g_act + r1);
            *(float2*)(g_act + r0) = make_float2(o[j][0]*inv0*g0.x, o[j][1]*inv0*g0.y);
            *(float2*)(g_act + r1) = make_float2(o[j][2]*inv1*g1.x, o[j][3]*inv1*g1.y);
        }
    }
}

// ============================================================================
// Kernel 3: out = act @ wo^T + bo  (fp16 m16n8k16 mma, cp.async staged wo)
// ============================================================================
__global__ __launch_bounds__(256, 2) void k3_out(
    const float* __restrict__ bo, float* __restrict__ out)
{
    extern __shared__ char smc[];
    char* wb[2] = { smc, smc + 64*WSB };

    const int tid  = threadIdx.x;
    const int warp = tid >> 5, lane = tid & 31;
    const int gr   = lane >> 2, gc = lane & 3;
    const int t0   = blockIdx.x * 128;

    // stage act -> fp16 xs
    #pragma unroll
    for (int s = 0; s < 16; s++) {
        const int idx = tid + 256*s;            // 4096 float4
        const int lt = idx >> 5, c0 = (idx & 31) * 4;
        const float4 a4 = *(const float4*)(g_act + (size_t)(t0+lt)*CIN + c0);
        char* dst = smc + lt*XSB + c0*2;
        *(__half2*)(dst)     = __floats2half2_rn(a4.x, a4.y);
        *(__half2*)(dst + 4) = __floats2half2_rn(a4.z, a4.w);
    }
    __syncthreads();

    const int m0 = warp * 16;
    uint32_t a[8][4];
    #pragma unroll
    for (int ks = 0; ks < 8; ks++) {
        const char* rp = smc + (m0+gr)*XSB + ks*32 + gc*4;
        a[ks][0] = *(const uint32_t*)(rp);
        a[ks][1] = *(const uint32_t*)(rp + 8*XSB);
        a[ks][2] = *(const uint32_t*)(rp + 16);
        a[ks][3] = *(const uint32_t*)(rp + 8*XSB + 16);
    }
    __syncthreads();     // xs consumed

    const uint32_t wbu[2] = { s2u(wb[0]), s2u(wb[1]) };
    #pragma unroll
    for (int q = 0; q < 2; q++) {
        const __half* src = g_wh + 4*16384 + q*8192;
        #pragma unroll
        for (int s = 0; s < 4; s++) {
            const int idx = tid + 256*s;
            const int o = idx >> 4, ch = idx & 15;
            cpa16(wbu[q] + o*WSB + ch*16, src + o*128 + ch*8);
        }
        CPA_COMMIT();
    }

    const int tok = t0 + m0 + gr;
    for (int hf = 0; hf < 2; hf++) {
        if (hf == 0) { CPA_WAIT(1); } else { CPA_WAIT(0); }
        __syncthreads();

        const char* wS = wb[hf];
        float acc[8][4];
        #pragma unroll
        for (int nt = 0; nt < 8; nt++)
            #pragma unroll
            for (int e = 0; e < 4; e++) acc[nt][e] = 0.f;

        #pragma unroll
        for (int ks = 0; ks < 8; ks++) {
            #pragma unroll
            for (int nt = 0; nt < 8; nt++) {
                const uint2 b = *(const uint2*)(wS + (nt*8+gr)*WSB + ks*32 + gc*8);
                mma_f16(acc[nt], a[ks][0], a[ks][1], a[ks][2], a[ks][3], b.x, b.y);
            }
        }

        #pragma unroll
        for (int nt = 0; nt < 8; nt++) {
            const int o = hf*64 + nt*8 + 2*gc;
            const float2 bov = __ldg((const float2*)(bo + o));
            *(float2*)(out + (size_t)tok*CIN + o) =
                make_float2(acc[nt][0]+bov.x, acc[nt][1]+bov.y);
            *(float2*)(out + (size_t)(tok+8)*CIN + o) =
                make_float2(acc[nt][2]+bov.x, acc[nt][3]+bov.y);
        }
    }
}

// ============================================================================
extern "C" void kernel_launch(void* const* d_in, const int* in_sizes, int n_in,
                              void* d_out, int out_size)
{
    const float* x     = (const float*)d_in[0];
    const float* mask  = (const float*)d_in[1];
    const float* gamma = (const float*)d_in[2];
    const float* beta  = (const float*)d_in[3];
    const float* wbias = (const float*)d_in[4];
    const float* wq    = (const float*)d_in[5];
    const float* wk    = (const float*)d_in[6];
    const float* wv    = (const float*)d_in[7];
    const float* wg    = (const float*)d_in[8];
    const float* wo    = (const float*)d_in[10];
    const float* bg    = (const float*)d_in[9];
    const float* bo    = (const float*)d_in[11];
    float* out = (float*)d_out;

    const int smem_gemm = 2 * 64 * WSB;                       // 36,864 B
    const int smem_attn = (NSEQ*KST*2 + NSEQ) * 4;            // 112,128 B

    cudaFuncSetAttribute(k1_ln_proj, cudaFuncAttributeMaxDynamicSharedMemorySize, smem_gemm);
    cudaFuncSetAttribute(k2_attn,   cudaFuncAttributeMaxDynamicSharedMemorySize, smem_attn);
    cudaFuncSetAttribute(k3_out,    cudaFuncAttributeMaxDynamicSharedMemorySize, smem_gemm);

    k0_prep  <<<320, 256>>>(wq, wk, wv, wg, wo);
    k1_ln_proj<<<NTOK/128, 256, smem_gemm>>>(x, gamma, beta, wbias, bg);
    k2_attn  <<<NSEQ*NH,  384, smem_attn>>>(mask);
    k3_out   <<<NTOK/128, 256, smem_gemm>>>(bo, out);
}

// round 13
// speedup vs baseline: 1.2632x; 1.1608x over previous
#include <cuda_runtime.h>
#include <cuda_bf16.h>
#include <cuda_fp16.h>
#include <cstdint>

#define NSEQ 384
#define CIN  128
#define NH   4
#define DH   32
#define NTOK (NSEQ*NSEQ)
#define LOG2E 1.4426950408889634f

// fp16 smem geometry (bytes)
#define XSB 272     // k1/k3 A rows: frag b32 loads bank-perfect
#define WSB 288     // k1/k3 W rows: LDS.64 frag loads bank-perfect
#define KHB 80      // k2 K rows (40 halves): b0/b1 4B loads bank-perfect (20*gr+gc distinct)

// ---- helpers ----
__device__ __forceinline__ uint32_t tf32u(float x) {
    uint32_t r; asm("cvt.rna.tf32.f32 %0, %1;" : "=r"(r) : "f"(x)); return r;
}
__device__ __forceinline__ float tf32f(float x) { return __uint_as_float(tf32u(x)); }
__device__ __forceinline__ float ex2(float x) {
    float r; asm("ex2.approx.f32 %0, %1;" : "=f"(r) : "f"(x)); return r;
}
__device__ __forceinline__ void mma_tf32(float c[4],
    uint32_t a0, uint32_t a1, uint32_t a2, uint32_t a3, uint32_t b0, uint32_t b1)
{
    asm("mma.sync.aligned.m16n8k8.row.col.f32.tf32.tf32.f32 "
        "{%0,%1,%2,%3}, {%4,%5,%6,%7}, {%8,%9}, {%0,%1,%2,%3};"
        : "+f"(c[0]), "+f"(c[1]), "+f"(c[2]), "+f"(c[3])
        : "r"(a0), "r"(a1), "r"(a2), "r"(a3), "r"(b0), "r"(b1));
}
__device__ __forceinline__ void mma_f16(float c[4],
    uint32_t a0, uint32_t a1, uint32_t a2, uint32_t a3, uint32_t b0, uint32_t b1)
{
    asm("mma.sync.aligned.m16n8k16.row.col.f32.f16.f16.f32 "
        "{%0,%1,%2,%3}, {%4,%5,%6,%7}, {%8,%9}, {%0,%1,%2,%3};"
        : "+f"(c[0]), "+f"(c[1]), "+f"(c[2]), "+f"(c[3])
        : "r"(a0), "r"(a1), "r"(a2), "r"(a3), "r"(b0), "r"(b1));
}
__device__ __forceinline__ uint32_t s2u(const void* p) {
    uint32_t a;
    asm("{ .reg .u64 t; cvta.to.shared.u64 t, %1; cvt.u32.u64 %0, t; }" : "=r"(a) : "l"(p));
    return a;
}
__device__ __forceinline__ void cpa16(uint32_t dst, const void* src) {
    asm volatile("cp.async.cg.shared.global [%0], [%1], 16;" :: "r"(dst), "l"(src));
}
#define CPA_COMMIT() asm volatile("cp.async.commit_group;" ::: "memory")
#define CPA_WAIT(n)  asm volatile("cp.async.wait_group %0;" :: "n"(n) : "memory")

// ---- scratch ----
__device__ __half g_qh[NSEQ*NH*NSEQ*DH];   // fp16, q pre-scaled by sc*log2e
__device__ __half g_kh[NSEQ*NH*NSEQ*DH];   // fp16
__device__ float  g_v [NSEQ*NH*NSEQ*DH];   // fp32 (tf32 bits) — AV stays tf32
__device__ float  g_act[(size_t)NTOK*CIN];
__device__ float  g_eb [NH*NTOK];          // ex2(tri-bias * log2e)
__device__ __align__(16) __half g_wh[5*CIN*CIN];  // fp16, k-pair permuted weights

// ============================================================================
// Kernel 0: weights -> fp16, k-pair permuted (B frag = one LDS.64)
// ============================================================================
__global__ void k0_prep(const float* __restrict__ wq, const float* __restrict__ wk,
                        const float* __restrict__ wv, const float* __restrict__ wg,
                        const float* __restrict__ wo)
{
    const int idx = blockIdx.x * 256 + threadIdx.x;      // 81920
    const int m   = idx >> 14;
    const int rem = idx & 16383;
    const int o   = rem >> 7, c = rem & 127;
    const float* srcs[5] = {wq, wk, wv, wg, wo};
    const float v = srcs[m][o*CIN + c];
    const int j    = (c >> 1) & 7;
    const int slot = 2*(j & 3) + (j >> 2);
    const int cperm = (c & ~15) | (slot << 1) | (c & 1);
    g_wh[m*16384 + o*128 + cperm] = __float2half_rn(v);
}

// ============================================================================
// Kernel 1: LayerNorm + q/k/v/gate projections (fp16 mma) + tri-bias.
// q/k written fp16; v fp32(tf32); gate fp32.
// ============================================================================
__global__ __launch_bounds__(256, 2) void k1_ln_proj(
    const float* __restrict__ x,   const float* __restrict__ gamma,
    const float* __restrict__ beta,const float* __restrict__ wbias,
    const float* __restrict__ bg)
{
    extern __shared__ char smc[];
    char* wb[2] = { smc, smc + 64*WSB };

    const int tid  = threadIdx.x;
    const int warp = tid >> 5, lane = tid & 31;
    const int gr   = lane >> 2, gc = lane & 3;
    const int t0   = blockIdx.x * 128;

    // ---- LayerNorm -> xs (fp16) ----
    const float4 gm = *(const float4*)(gamma + lane*4);
    const float4 bt = *(const float4*)(beta  + lane*4);
    for (int kk = 0; kk < 16; kk++) {
        const int lt = warp*16 + kk;
        const float4 xv = *(const float4*)(x + (size_t)(t0+lt)*CIN + lane*4);
        float s = xv.x + xv.y + xv.z + xv.w;
        #pragma unroll
        for (int o = 16; o; o >>= 1) s += __shfl_xor_sync(0xffffffffu, s, o);
        const float mu = s * (1.0f/128.0f);
        const float d0 = xv.x-mu, d1 = xv.y-mu, d2 = xv.z-mu, d3 = xv.w-mu;
        float vs = d0*d0 + d1*d1 + d2*d2 + d3*d3;
        #pragma unroll
        for (int o = 16; o; o >>= 1) vs += __shfl_xor_sync(0xffffffffu, vs, o);
        const float rs = rsqrtf(vs * (1.0f/128.0f) + 1e-5f);
        const __half2 h01 = __floats2half2_rn(d0*rs*gm.x + bt.x, d1*rs*gm.y + bt.y);
        const __half2 h23 = __floats2half2_rn(d2*rs*gm.z + bt.z, d3*rs*gm.w + bt.w);
        char* dst = smc + lt*XSB + lane*8;
        *(__half2*)(dst)     = h01;
        *(__half2*)(dst + 4) = h23;
    }
    __syncthreads();

    // ---- tri-bias projection -> multiplicative ex2 form ----
    {
        const int lt = tid & 127;
        const int h0 = (tid >> 7) * 2;
        #pragma unroll
        for (int hh = 0; hh < 2; hh++) {
            const int h = h0 + hh;
            float sacc = 0.f;
            #pragma unroll 8
            for (int c0 = 0; c0 < CIN; c0 += 2) {
                const float2 xf = __half22float2(*(const __half2*)(smc + lt*XSB + c0*2));
                const float2 wv = *(const float2*)(wbias + h*CIN + c0);
                sacc += xf.x*wv.x + xf.y*wv.y;
            }
            g_eb[h*NTOK + t0 + lt] = ex2(sacc * LOG2E);
        }
    }

    // ---- A fragments ----
    const int m0 = warp * 16;
    uint32_t a[8][4];
    #pragma unroll
    for (int ks = 0; ks < 8; ks++) {
        const char* rp = smc + (m0+gr)*XSB + ks*32 + gc*4;
        a[ks][0] = *(const uint32_t*)(rp);
        a[ks][1] = *(const uint32_t*)(rp + 8*XSB);
        a[ks][2] = *(const uint32_t*)(rp + 16);
        a[ks][3] = *(const uint32_t*)(rp + 8*XSB + 16);
    }
    __syncthreads();

    const uint32_t wbu[2] = { s2u(wb[0]), s2u(wb[1]) };
    #pragma unroll
    for (int q = 0; q < 2; q++) {
        const __half* src = g_wh + q*8192;
        #pragma unroll
        for (int s = 0; s < 4; s++) {
            const int idx = tid + 256*s;
            const int o = idx >> 4, ch = idx & 15;
            cpa16(wbu[q] + o*WSB + ch*16, src + o*128 + ch*8);
        }
        CPA_COMMIT();
    }

    const int i_row = t0 / NSEQ;
    const int jb    = t0 % NSEQ;
    const int j0    = jb + m0 + gr;

    for (int p = 0; p < 8; p++) {
        if (p == 7) { CPA_WAIT(0); } else { CPA_WAIT(1); }
        __syncthreads();

        const char* wS = wb[p & 1];
        float acc[8][4];
        #pragma unroll
        for (int nt = 0; nt < 8; nt++)
            #pragma unroll
            for (int e = 0; e < 4; e++) acc[nt][e] = 0.f;

        #pragma unroll
        for (int ks = 0; ks < 8; ks++) {
            #pragma unroll
            for (int nt = 0; nt < 8; nt++) {
                const uint2 b = *(const uint2*)(wS + (nt*8+gr)*WSB + ks*32 + gc*8);
                mma_f16(acc[nt], a[ks][0], a[ks][1], a[ks][2], a[ks][3], b.x, b.y);
            }
        }
        __syncthreads();

        if (p + 2 < 8) {
            const __half* src = g_wh + (p+2)*8192;
            #pragma unroll
            for (int s = 0; s < 4; s++) {
                const int idx = tid + 256*s;
                const int o = idx >> 4, ch = idx & 15;
                cpa16(wbu[p & 1] + o*WSB + ch*16, src + o*128 + ch*8);
            }
            CPA_COMMIT();
        }

        // ---- epilogue ----
        const int grp = p >> 1;
        const int ob  = (p & 1) * 64;
        if (grp < 2) {
            __half* dst = (grp==0) ? g_qh : g_kh;
            const float sc = (grp==0) ? 0.17677669529663687f * LOG2E : 1.0f;
            #pragma unroll
            for (int nt = 0; nt < 8; nt++) {
                const int o = ob + nt*8 + 2*gc;
                const int h = o >> 5, d = o & 31;
                __half* ptr = dst + ((size_t)(i_row*NH + h)*NSEQ + j0)*DH + d;
                *(__half2*)ptr          = __floats2half2_rn(acc[nt][0]*sc, acc[nt][1]*sc);
                *(__half2*)(ptr + 8*DH) = __floats2half2_rn(acc[nt][2]*sc, acc[nt][3]*sc);
            }
        } else if (grp == 2) {
            #pragma unroll
            for (int nt = 0; nt < 8; nt++) {
                const int o = ob + nt*8 + 2*gc;
                const int h = o >> 5, d = o & 31;
                float* ptr = g_v + ((size_t)(i_row*NH + h)*NSEQ + j0)*DH + d;
                *(float2*)ptr          = make_float2(tf32f(acc[nt][0]), tf32f(acc[nt][1]));
                *(float2*)(ptr + 8*DH) = make_float2(tf32f(acc[nt][2]), tf32f(acc[nt][3]));
            }
        } else {
            const int tok = t0 + m0 + gr;
            #pragma unroll
            for (int nt = 0; nt < 8; nt++) {
                const int o = ob + nt*8 + 2*gc;
                const float2 bgv = __ldg((const float2*)(bg + o));
                float2 lo, hi;
                lo.x = 1.0f/(1.0f+__expf(-(acc[nt][0]+bgv.x)));
                lo.y = 1.0f/(1.0f+__expf(-(acc[nt][1]+bgv.y)));
                hi.x = 1.0f/(1.0f+__expf(-(acc[nt][2]+bgv.x)));
                hi.y = 1.0f/(1.0f+__expf(-(acc[nt][3]+bgv.y)));
                *(float2*)(g_act + (size_t)tok*CIN + o)     = lo;
                *(float2*)(g_act + (size_t)(tok+8)*CIN + o) = hi;
            }
        }
    }
}

// ============================================================================
// Kernel 2: flash attention per (i,h). QK in fp16 m16n8k16 (half the MMAs);
// AV stays tf32 (P magnitudes unsafe for fp16). 384 thr, occ 2.
// ============================================================================
#define KST 36                   // V stride (floats)
#define K_OFF 0                  // K fp16 [384][40 halves]
#define V_OFF (NSEQ*KHB)         // 30720
#define M_OFF (V_OFF + NSEQ*KST*4)  // 86016

__global__ __launch_bounds__(384, 2) void k2_attn(const float* __restrict__ mask)
{
    extern __shared__ char smc[];
    __half* Ksm = (__half*)(smc + K_OFF);
    float*  Vsm = (float*)(smc + V_OFF);
    float*  msm = (float*)(smc + M_OFF);

    const int tid  = threadIdx.x;
    const int warp = tid >> 5, lane = tid & 31;
    const int gr   = lane >> 2, gc = lane & 3;
    const int src0 = (lane & ~3) | ((lane & 3) >> 1);
    const int src1 = src0 + 2;
    const bool sel = (lane & 1);
    const int vbase = (gr & 3) + ((gr >> 2) << 4);
    const int i = blockIdx.x >> 2;
    const int h = blockIdx.x & 3;
    const int base = ((i*NH) + h) * NSEQ * DH;

    // K: fp16 raw async copy (rows 64B -> 4 chunks; stride 80B)
    {
        const uint32_t ku = s2u(Ksm);
        #pragma unroll
        for (int it = 0; it < 4; it++) {
            const int idx = tid + 384*it;          // 1536 chunks
            const int j = idx >> 2, ch = idx & 3;
            cpa16(ku + j*KHB + ch*16, g_kh + base + j*DH + ch*8);
        }
        CPA_COMMIT();
    }
    // V: [key][p(dim)] scatter (fp32)
    #pragma unroll
    for (int it = 0; it < 8; it++) {
        const int idx = tid + 384*it;
        const int j = idx >> 3, dq = (idx & 7) * 4;
        const float4 vv = *(const float4*)(g_v + base + j*DH + dq);
        const int pp = 4*(dq >> 3) + ((dq & 4) << 2);
        *(float4*)(Vsm + j*KST + pp) = vv;
    }
    if (tid < NSEQ)
        msm[tid] = ex2((mask[i*NSEQ + tid] - 1.0f) * (1e9f * LOG2E));
    CPA_WAIT(0);
    __syncthreads();

    const float* __restrict__ tb = g_eb + h*NTOK;

    for (int t = 0; t < 2; t++) {
        const int jq0 = (warp + 12*t) * 16;

        // Q fragments: fp16, 2 k-steps of 16
        uint32_t qa[2][4];
        const uint32_t* qp  = (const uint32_t*)(g_qh + base + (jq0+gr)*DH);
        const uint32_t* qp8 = qp + 8*(DH/2);
        #pragma unroll
        for (int ks = 0; ks < 2; ks++) {
            qa[ks][0] = __ldg(qp  + ks*8 + gc);
            qa[ks][1] = __ldg(qp8 + ks*8 + gc);
            qa[ks][2] = __ldg(qp  + ks*8 + gc + 4);
            qa[ks][3] = __ldg(qp8 + ks*8 + gc + 4);
        }

        float s0 = 0.f, s1 = 0.f;
        float o[4][4];
        #pragma unroll
        for (int j = 0; j < 4; j++)
            #pragma unroll
            for (int e = 0; e < 4; e++) o[j][e] = 0.f;

        const float* tbr0 = tb + (size_t)(jq0+gr)*NSEQ;
        const float* tbr1 = tbr0 + 8*NSEQ;

        for (int n0 = 0; n0 < NSEQ; n0 += 32) {
            // ---- QK MMA: fp16, 8 MMAs/chunk ----
            float c[4][4];
            #pragma unroll
            for (int j = 0; j < 4; j++) {
                #pragma unroll
                for (int e = 0; e < 4; e++) c[j][e] = 0.f;
                const uint32_t* kb =
                    (const uint32_t*)((const char*)Ksm + (n0 + 8*j + gr)*KHB);
                #pragma unroll
                for (int ks = 0; ks < 2; ks++) {
                    const uint32_t b0 = kb[ks*8 + gc];
                    const uint32_t b1 = kb[ks*8 + gc + 4];
                    mma_f16(c[j], qa[ks][0], qa[ks][1], qa[ks][2], qa[ks][3], b0, b1);
                }
            }

            // ---- p = ex2(qk) * eb * mask ----
            #pragma unroll
            for (int j = 0; j < 4; j++) {
                const float2 e0 = __ldg((const float2*)(tbr0 + n0 + 8*j + 2*gc));
                const float2 e1 = __ldg((const float2*)(tbr1 + n0 + 8*j + 2*gc));
                const float2 mk = *(const float2*)(msm + n0 + 8*j + 2*gc);
                const float p0 = ex2(c[j][0]) * (e0.x*mk.x);
                const float p1 = ex2(c[j][1]) * (e0.y*mk.y);
                const float p2 = ex2(c[j][2]) * (e1.x*mk.x);
                const float p3 = ex2(c[j][3]) * (e1.y*mk.y);
                s0 += p0 + p1; s1 += p2 + p3;
                c[j][0] = p0; c[j][1] = p1; c[j][2] = p2; c[j][3] = p3;
            }

            // ---- AV: tf32, shuffle refragment, scattered Vsm ----
            #pragma unroll
            for (int ks = 0; ks < 4; ks++) {
                const float x0 = __shfl_sync(0xffffffffu, c[ks][0], src0);
                const float x1 = __shfl_sync(0xffffffffu, c[ks][1], src0);
                const float x2 = __shfl_sync(0xffffffffu, c[ks][2], src0);
                const float x3 = __shfl_sync(0xffffffffu, c[ks][3], src0);
                const float y0 = __shfl_sync(0xffffffffu, c[ks][0], src1);
                const float y1 = __shfl_sync(0xffffffffu, c[ks][1], src1);
                const float y2 = __shfl_sync(0xffffffffu, c[ks][2], src1);
                const float y3 = __shfl_sync(0xffffffffu, c[ks][3], src1);
                const uint32_t a0 = __float_as_uint(sel ? x1 : x0);
                const uint32_t a1 = __float_as_uint(sel ? x3 : x2);
                const uint32_t a2 = __float_as_uint(sel ? y1 : y0);
                const uint32_t a3 = __float_as_uint(sel ? y3 : y2);
                const float* vr0 = Vsm + (n0 + 8*ks + gc)*KST + vbase;
                const float* vr1 = vr0 + 4*KST;
                #pragma unroll
                for (int j = 0; j < 4; j++) {
                    const uint32_t b0 = __float_as_uint(vr0[4*j]);
                    const uint32_t b1 = __float_as_uint(vr1[4*j]);
                    mma_tf32(o[j], a0, a1, a2, a3, b0, b1);
                }
            }
        }

        s0 += __shfl_xor_sync(0xffffffffu, s0, 1);
        s0 += __shfl_xor_sync(0xffffffffu, s0, 2);
        s1 += __shfl_xor_sync(0xffffffffu, s1, 1);
        s1 += __shfl_xor_sync(0xffffffffu, s1, 2);
        const float inv0 = 1.0f / s0, inv1 = 1.0f / s1;

        #pragma unroll
        for (int j = 0; j < 4; j++) {
            const int col = h*DH + 8*j + 2*gc;
            const size_t r0 = (size_t)(i*NSEQ + jq0 + gr)*CIN + col;
            const size_t r1 = (size_t)(i*NSEQ + jq0 + gr + 8)*CIN + col;
            const float2 g0 = *(const float2*)(g_act + r0);
            const float2 g1 = *(const float2*)(g_act + r1);
            *(float2*)(g_act + r0) = make_float2(o[j][0]*inv0*g0.x, o[j][1]*inv0*g0.y);
            *(float2*)(g_act + r1) = make_float2(o[j][2]*inv1*g1.x, o[j][3]*inv1*g1.y);
        }
    }
}

// ============================================================================
// Kernel 3: out = act @ wo^T + bo  (fp16 mma — unchanged R11)
// ============================================================================
__global__ __launch_bounds__(256, 2) void k3_out(
    const float* __restrict__ bo, float* __restrict__ out)
{
    extern __shared__ char smc[];
    char* wb[2] = { smc, smc + 64*WSB };

    const int tid  = threadIdx.x;
    const int warp = tid >> 5, lane = tid & 31;
    const int gr   = lane >> 2, gc = lane & 3;
    const int t0   = blockIdx.x * 128;

    #pragma unroll
    for (int s = 0; s < 16; s++) {
        const int idx = tid + 256*s;
        const int lt = idx >> 5, c0 = (idx & 31) * 4;
        const float4 a4 = *(const float4*)(g_act + (size_t)(t0+lt)*CIN + c0);
        char* dst = smc + lt*XSB + c0*2;
        *(__half2*)(dst)     = __floats2half2_rn(a4.x, a4.y);
        *(__half2*)(dst + 4) = __floats2half2_rn(a4.z, a4.w);
    }
    __syncthreads();

    const int m0 = warp * 16;
    uint32_t a[8][4];
    #pragma unroll
    for (int ks = 0; ks < 8; ks++) {
        const char* rp = smc + (m0+gr)*XSB + ks*32 + gc*4;
        a[ks][0] = *(const uint32_t*)(rp);
        a[ks][1] = *(const uint32_t*)(rp + 8*XSB);
        a[ks][2] = *(const uint32_t*)(rp + 16);
        a[ks][3] = *(const uint32_t*)(rp + 8*XSB + 16);
    }
    __syncthreads();

    const uint32_t wbu[2] = { s2u(wb[0]), s2u(wb[1]) };
    #pragma unroll
    for (int q = 0; q < 2; q++) {
        const __half* src = g_wh + 4*16384 + q*8192;
        #pragma unroll
        for (int s = 0; s < 4; s++) {
            const int idx = tid + 256*s;
            const int o = idx >> 4, ch = idx & 15;
            cpa16(wbu[q] + o*WSB + ch*16, src + o*128 + ch*8);
        }
        CPA_COMMIT();
    }

    const int tok = t0 + m0 + gr;
    for (int hf = 0; hf < 2; hf++) {
        if (hf == 0) { CPA_WAIT(1); } else { CPA_WAIT(0); }
        __syncthreads();

        const char* wS = wb[hf];
        float acc[8][4];
        #pragma unroll
        for (int nt = 0; nt < 8; nt++)
            #pragma unroll
            for (int e = 0; e < 4; e++) acc[nt][e] = 0.f;

        #pragma unroll
        for (int ks = 0; ks < 8; ks++) {
            #pragma unroll
            for (int nt = 0; nt < 8; nt++) {
                const uint2 b = *(const uint2*)(wS + (nt*8+gr)*WSB + ks*32 + gc*8);
                mma_f16(acc[nt], a[ks][0], a[ks][1], a[ks][2], a[ks][3], b.x, b.y);
            }
        }

        #pragma unroll
        for (int nt = 0; nt < 8; nt++) {
            const int o = hf*64 + nt*8 + 2*gc;
            const float2 bov = __ldg((const float2*)(bo + o));
            *(float2*)(out + (size_t)tok*CIN + o) =
                make_float2(acc[nt][0]+bov.x, acc[nt][1]+bov.y);
            *(float2*)(out + (size_t)(tok+8)*CIN + o) =
                make_float2(acc[nt][2]+bov.x, acc[nt][3]+bov.y);
        }
    }
}

// ============================================================================
extern "C" void kernel_launch(void* const* d_in, const int* in_sizes, int n_in,
                              void* d_out, int out_size)
{
    const float* x     = (const float*)d_in[0];
    const float* mask  = (const float*)d_in[1];
    const float* gamma = (const float*)d_in[2];
    const float* beta  = (const float*)d_in[3];
    const float* wbias = (const float*)d_in[4];
    const float* wq    = (const float*)d_in[5];
    const float* wk    = (const float*)d_in[6];
    const float* wv    = (const float*)d_in[7];
    const float* wg    = (const float*)d_in[8];
    const float* bg    = (const float*)d_in[9];
    const float* wo    = (const float*)d_in[10];
    const float* bo    = (const float*)d_in[11];
    float* out = (float*)d_out;

    const int smem_gemm = 2 * 64 * WSB;                       // 36,864 B
    const int smem_attn = M_OFF + NSEQ*4;                     // 87,552 B

    cudaFuncSetAttribute(k1_ln_proj, cudaFuncAttributeMaxDynamicSharedMemorySize, smem_gemm);
    cudaFuncSetAttribute(k2_attn,   cudaFuncAttributeMaxDynamicSharedMemorySize, smem_attn);
    cudaFuncSetAttribute(k3_out,    cudaFuncAttributeMaxDynamicSharedMemorySize, smem_gemm);

    k0_prep  <<<320, 256>>>(wq, wk, wv, wg, wo);
    k1_ln_proj<<<NTOK/128, 256, smem_gemm>>>(x, gamma, beta, wbias, bg);
    k2_attn  <<<NSEQ*NH,  384, smem_attn>>>(mask);
    k3_out   <<<NTOK/128, 256, smem_gemm>>>(bo, out);
}

// round 14
// speedup vs baseline: 1.5271x; 1.2089x over previous
#include <cuda_runtime.h>
#include <cuda_bf16.h>
#include <cuda_fp16.h>
#include <cstdint>

#define NSEQ 384
#define CIN  128
#define NH   4
#define DH   32
#define NTOK (NSEQ*NSEQ)
#define LOG2E 1.4426950408889634f

// fp16 smem geometry (bytes)
#define XSB 272     // k1/k3 A rows: frag b32 loads bank-perfect
#define WSB 288     // k1/k3 W rows: LDS.64 frag loads bank-perfect
#define KHB 80      // k2 K rows (40 halves): b32 loads bank-perfect
#define VSTH 392    // k2 V^T rows (halves): b32 loads bank-perfect (8*dim+gc)

// ---- helpers ----
__device__ __forceinline__ float ex2(float x) {
    float r; asm("ex2.approx.f32 %0, %1;" : "=f"(r) : "f"(x)); return r;
}
__device__ __forceinline__ void mma_f16(float c[4],
    uint32_t a0, uint32_t a1, uint32_t a2, uint32_t a3, uint32_t b0, uint32_t b1)
{
    asm("mma.sync.aligned.m16n8k16.row.col.f32.f16.f16.f32 "
        "{%0,%1,%2,%3}, {%4,%5,%6,%7}, {%8,%9}, {%0,%1,%2,%3};"
        : "+f"(c[0]), "+f"(c[1]), "+f"(c[2]), "+f"(c[3])
        : "r"(a0), "r"(a1), "r"(a2), "r"(a3), "r"(b0), "r"(b1));
}
__device__ __forceinline__ uint32_t s2u(const void* p) {
    uint32_t a;
    asm("{ .reg .u64 t; cvta.to.shared.u64 t, %1; cvt.u32.u64 %0, t; }" : "=r"(a) : "l"(p));
    return a;
}
__device__ __forceinline__ void cpa16(uint32_t dst, const void* src) {
    asm volatile("cp.async.cg.shared.global [%0], [%1], 16;" :: "r"(dst), "l"(src));
}
#define CPA_COMMIT() asm volatile("cp.async.commit_group;" ::: "memory")
#define CPA_WAIT(n)  asm volatile("cp.async.wait_group %0;" :: "n"(n) : "memory")
__device__ __forceinline__ uint32_t pkh2(float a, float b) {
    __half2 h = __floats2half2_rn(a, b);
    return *(uint32_t*)&h;
}

// ---- scratch ----
__device__ __half g_qh[NSEQ*NH*NSEQ*DH];   // fp16, q pre-scaled by sc*log2e
__device__ __half g_kh[NSEQ*NH*NSEQ*DH];   // fp16
__device__ __half g_vh[NSEQ*NH*NSEQ*DH];   // fp16
__device__ float  g_act[(size_t)NTOK*CIN];
__device__ float  g_eb [NH*NTOK];          // ex2(tri-bias*log2e - 6)  (scaled, cancels in softmax)
__device__ __align__(16) __half g_wh[5*CIN*CIN];  // fp16, k-pair permuted weights

// ============================================================================
// Kernel 0: weights -> fp16, k-pair permuted (B frag = one LDS.64)
// ============================================================================
__global__ void k0_prep(const float* __restrict__ wq, const float* __restrict__ wk,
                        const float* __restrict__ wv, const float* __restrict__ wg,
                        const float* __restrict__ wo)
{
    const int idx = blockIdx.x * 256 + threadIdx.x;      // 81920
    const int m   = idx >> 14;
    const int rem = idx & 16383;
    const int o   = rem >> 7, c = rem & 127;
    const float* srcs[5] = {wq, wk, wv, wg, wo};
    const float v = srcs[m][o*CIN + c];
    const int j    = (c >> 1) & 7;
    const int slot = 2*(j & 3) + (j >> 2);
    const int cperm = (c & ~15) | (slot << 1) | (c & 1);
    g_wh[m*16384 + o*128 + cperm] = __float2half_rn(v);
}

// ============================================================================
// Kernel 1: LayerNorm + q/k/v/gate projections (fp16 mma) + tri-bias.
// q/k/v all written fp16; gate fp32.
// ============================================================================
__global__ __launch_bounds__(256, 2) void k1_ln_proj(
    const float* __restrict__ x,   const float* __restrict__ gamma,
    const float* __restrict__ beta,const float* __restrict__ wbias,
    const float* __restrict__ bg)
{
    extern __shared__ char smc[];
    char* wb[2] = { smc, smc + 64*WSB };

    const int tid  = threadIdx.x;
    const int warp = tid >> 5, lane = tid & 31;
    const int gr   = lane >> 2, gc = lane & 3;
    const int t0   = blockIdx.x * 128;

    // ---- LayerNorm -> xs (fp16) ----
    const float4 gm = *(const float4*)(gamma + lane*4);
    const float4 bt = *(const float4*)(beta  + lane*4);
    for (int kk = 0; kk < 16; kk++) {
        const int lt = warp*16 + kk;
        const float4 xv = *(const float4*)(x + (size_t)(t0+lt)*CIN + lane*4);
        float s = xv.x + xv.y + xv.z + xv.w;
        #pragma unroll
        for (int o = 16; o; o >>= 1) s += __shfl_xor_sync(0xffffffffu, s, o);
        const float mu = s * (1.0f/128.0f);
        const float d0 = xv.x-mu, d1 = xv.y-mu, d2 = xv.z-mu, d3 = xv.w-mu;
        float vs = d0*d0 + d1*d1 + d2*d2 + d3*d3;
        #pragma unroll
        for (int o = 16; o; o >>= 1) vs += __shfl_xor_sync(0xffffffffu, vs, o);
        const float rs = rsqrtf(vs * (1.0f/128.0f) + 1e-5f);
        const __half2 h01 = __floats2half2_rn(d0*rs*gm.x + bt.x, d1*rs*gm.y + bt.y);
        const __half2 h23 = __floats2half2_rn(d2*rs*gm.z + bt.z, d3*rs*gm.w + bt.w);
        char* dst = smc + lt*XSB + lane*8;
        *(__half2*)(dst)     = h01;
        *(__half2*)(dst + 4) = h23;
    }
    __syncthreads();

    // ---- tri-bias projection -> multiplicative ex2 form (2^-6 safety shift) ----
    {
        const int lt = tid & 127;
        const int h0 = (tid >> 7) * 2;
        #pragma unroll
        for (int hh = 0; hh < 2; hh++) {
            const int h = h0 + hh;
            float sacc = 0.f;
            #pragma unroll 8
            for (int c0 = 0; c0 < CIN; c0 += 2) {
                const float2 xf = __half22float2(*(const __half2*)(smc + lt*XSB + c0*2));
                const float2 wv = *(const float2*)(wbias + h*CIN + c0);
                sacc += xf.x*wv.x + xf.y*wv.y;
            }
            g_eb[h*NTOK + t0 + lt] = ex2(sacc * LOG2E - 6.0f);
        }
    }

    // ---- A fragments ----
    const int m0 = warp * 16;
    uint32_t a[8][4];
    #pragma unroll
    for (int ks = 0; ks < 8; ks++) {
        const char* rp = smc + (m0+gr)*XSB + ks*32 + gc*4;
        a[ks][0] = *(const uint32_t*)(rp);
        a[ks][1] = *(const uint32_t*)(rp + 8*XSB);
        a[ks][2] = *(const uint32_t*)(rp + 16);
        a[ks][3] = *(const uint32_t*)(rp + 8*XSB + 16);
    }
    __syncthreads();

    const uint32_t wbu[2] = { s2u(wb[0]), s2u(wb[1]) };
    #pragma unroll
    for (int q = 0; q < 2; q++) {
        const __half* src = g_wh + q*8192;
        #pragma unroll
        for (int s = 0; s < 4; s++) {
            const int idx = tid + 256*s;
            const int o = idx >> 4, ch = idx & 15;
            cpa16(wbu[q] + o*WSB + ch*16, src + o*128 + ch*8);
        }
        CPA_COMMIT();
    }

    const int i_row = t0 / NSEQ;
    const int jb    = t0 % NSEQ;
    const int j0    = jb + m0 + gr;

    for (int p = 0; p < 8; p++) {
        if (p == 7) { CPA_WAIT(0); } else { CPA_WAIT(1); }
        __syncthreads();

        const char* wS = wb[p & 1];
        float acc[8][4];
        #pragma unroll
        for (int nt = 0; nt < 8; nt++)
            #pragma unroll
            for (int e = 0; e < 4; e++) acc[nt][e] = 0.f;

        #pragma unroll
        for (int ks = 0; ks < 8; ks++) {
            #pragma unroll
            for (int nt = 0; nt < 8; nt++) {
                const uint2 b = *(const uint2*)(wS + (nt*8+gr)*WSB + ks*32 + gc*8);
                mma_f16(acc[nt], a[ks][0], a[ks][1], a[ks][2], a[ks][3], b.x, b.y);
            }
        }
        __syncthreads();

        if (p + 2 < 8) {
            const __half* src = g_wh + (p+2)*8192;
            #pragma unroll
            for (int s = 0; s < 4; s++) {
                const int idx = tid + 256*s;
                const int o = idx >> 4, ch = idx & 15;
                cpa16(wbu[p & 1] + o*WSB + ch*16, src + o*128 + ch*8);
            }
            CPA_COMMIT();
        }

        // ---- epilogue ----
        const int grp = p >> 1;
        const int ob  = (p & 1) * 64;
        if (grp < 3) {
            __half* dst = (grp==0) ? g_qh : (grp==1) ? g_kh : g_vh;
            const float sc = (grp==0) ? 0.17677669529663687f * LOG2E : 1.0f;
            #pragma unroll
            for (int nt = 0; nt < 8; nt++) {
                const int o = ob + nt*8 + 2*gc;
                const int h = o >> 5, d = o & 31;
                __half* ptr = dst + ((size_t)(i_row*NH + h)*NSEQ + j0)*DH + d;
                *(__half2*)ptr          = __floats2half2_rn(acc[nt][0]*sc, acc[nt][1]*sc);
                *(__half2*)(ptr + 8*DH) = __floats2half2_rn(acc[nt][2]*sc, acc[nt][3]*sc);
            }
        } else {
            const int tok = t0 + m0 + gr;
            #pragma unroll
            for (int nt = 0; nt < 8; nt++) {
                const int o = ob + nt*8 + 2*gc;
                const float2 bgv = __ldg((const float2*)(bg + o));
                float2 lo, hi;
                lo.x = 1.0f/(1.0f+__expf(-(acc[nt][0]+bgv.x)));
                lo.y = 1.0f/(1.0f+__expf(-(acc[nt][1]+bgv.y)));
                hi.x = 1.0f/(1.0f+__expf(-(acc[nt][2]+bgv.x)));
                hi.y = 1.0f/(1.0f+__expf(-(acc[nt][3]+bgv.y)));
                *(float2*)(g_act + (size_t)tok*CIN + o)     = lo;
                *(float2*)(g_act + (size_t)(tok+8)*CIN + o) = hi;
            }
        }
    }
}

// ============================================================================
// Kernel 2: flash attention per (i,h), fully fp16 MMA (QK and AV).
// AV A-fragment == QK C-fragment (no shuffles); V^T fp16 in smem.
// 384 thr, occ 2. Multiplicative bias with 2^-6 shift (cancels in normalize).
// ============================================================================
#define K_OFF 0                        // K fp16 [384][40 halves]  30720 B
#define V_OFF (NSEQ*KHB)               // V^T fp16 [32][392 halves] 25088 B
#define M_OFF (V_OFF + DH*VSTH*2)      // msm fp32 [384]
#define K2_SMEM (M_OFF + NSEQ*4)

__global__ __launch_bounds__(384, 2) void k2_attn(const float* __restrict__ mask)
{
    extern __shared__ char smc[];
    __half* Ksm = (__half*)(smc + K_OFF);
    __half* VT  = (__half*)(smc + V_OFF);
    float*  msm = (float*)(smc + M_OFF);

    const int tid  = threadIdx.x;
    const int warp = tid >> 5, lane = tid & 31;
    const int gr   = lane >> 2, gc = lane & 3;
    const int i = blockIdx.x >> 2;
    const int h = blockIdx.x & 3;
    const int base = ((i*NH) + h) * NSEQ * DH;

    // K: fp16 raw async copy
    {
        const uint32_t ku = s2u(Ksm);
        #pragma unroll
        for (int it = 0; it < 4; it++) {
            const int idx = tid + 384*it;          // 1536 chunks
            const int j = idx >> 2, ch = idx & 3;
            cpa16(ku + j*KHB + ch*16, g_kh + base + j*DH + ch*8);
        }
        CPA_COMMIT();
    }
    // V: transpose to VT[dim][key] fp16 (coalesced reads, ~4-way STS conflicts)
    #pragma unroll
    for (int it = 0; it < 16; it++) {
        const int idx = tid + 384*it;              // 6144 uint32
        const int j = idx >> 4, dp = idx & 15;
        const __half2 hv = *(const __half2*)(g_vh + base + j*DH + dp*2);
        VT[(2*dp)*VSTH + j]   = __low2half(hv);
        VT[(2*dp+1)*VSTH + j] = __high2half(hv);
    }
    if (tid < NSEQ)
        msm[tid] = ex2((mask[i*NSEQ + tid] - 1.0f) * (1e9f * LOG2E));
    CPA_WAIT(0);
    __syncthreads();

    const float* __restrict__ tb = g_eb + h*NTOK;
    const uint32_t* vt32 = (const uint32_t*)VT;

    for (int t = 0; t < 2; t++) {
        const int jq0 = (warp + 12*t) * 16;

        // Q fragments: fp16, 2 k-steps of 16
        uint32_t qa[2][4];
        const uint32_t* qp  = (const uint32_t*)(g_qh + base + (jq0+gr)*DH);
        const uint32_t* qp8 = qp + 8*(DH/2);
        #pragma unroll
        for (int ks = 0; ks < 2; ks++) {
            qa[ks][0] = __ldg(qp  + ks*8 + gc);
            qa[ks][1] = __ldg(qp8 + ks*8 + gc);
            qa[ks][2] = __ldg(qp  + ks*8 + gc + 4);
            qa[ks][3] = __ldg(qp8 + ks*8 + gc + 4);
        }

        float s0 = 0.f, s1 = 0.f;
        float o[4][4];
        #pragma unroll
        for (int j = 0; j < 4; j++)
            #pragma unroll
            for (int e = 0; e < 4; e++) o[j][e] = 0.f;

        const float* tbr0 = tb + (size_t)(jq0+gr)*NSEQ;
        const float* tbr1 = tbr0 + 8*NSEQ;

        for (int n0 = 0; n0 < NSEQ; n0 += 32) {
            // ---- QK MMA: fp16 ----
            float c[4][4];
            #pragma unroll
            for (int j = 0; j < 4; j++) {
                #pragma unroll
                for (int e = 0; e < 4; e++) c[j][e] = 0.f;
                const uint32_t* kb =
                    (const uint32_t*)((const char*)Ksm + (n0 + 8*j + gr)*KHB);
                #pragma unroll
                for (int ks = 0; ks < 2; ks++) {
                    const uint32_t b0 = kb[ks*8 + gc];
                    const uint32_t b1 = kb[ks*8 + gc + 4];
                    mma_f16(c[j], qa[ks][0], qa[ks][1], qa[ks][2], qa[ks][3], b0, b1);
                }
            }

            // ---- p = ex2(qk) * eb * mask  (eb carries 2^-6 shift) ----
            #pragma unroll
            for (int j = 0; j < 4; j++) {
                const float2 e0 = __ldg((const float2*)(tbr0 + n0 + 8*j + 2*gc));
                const float2 e1 = __ldg((const float2*)(tbr1 + n0 + 8*j + 2*gc));
                const float2 mk = *(const float2*)(msm + n0 + 8*j + 2*gc);
                const float p0 = ex2(c[j][0]) * (e0.x*mk.x);
                const float p1 = ex2(c[j][1]) * (e0.y*mk.y);
                const float p2 = ex2(c[j][2]) * (e1.x*mk.x);
                const float p3 = ex2(c[j][3]) * (e1.y*mk.y);
                s0 += p0 + p1; s1 += p2 + p3;
                c[j][0] = p0; c[j][1] = p1; c[j][2] = p2; c[j][3] = p3;
            }

            // ---- AV: fp16; A-frag = QK C-frag (no shuffles) ----
            #pragma unroll
            for (int ks = 0; ks < 2; ks++) {
                const uint32_t a0 = pkh2(c[2*ks  ][0], c[2*ks  ][1]);
                const uint32_t a1 = pkh2(c[2*ks  ][2], c[2*ks  ][3]);
                const uint32_t a2 = pkh2(c[2*ks+1][0], c[2*ks+1][1]);
                const uint32_t a3 = pkh2(c[2*ks+1][2], c[2*ks+1][3]);
                const int kk = (n0 + 16*ks) >> 1;
                #pragma unroll
                for (int j = 0; j < 4; j++) {
                    const uint32_t* vr = vt32 + (8*j + gr)*(VSTH/2) + kk;
                    mma_f16(o[j], a0, a1, a2, a3, vr[gc], vr[gc + 4]);
                }
            }
        }

        s0 += __shfl_xor_sync(0xffffffffu, s0, 1);
        s0 += __shfl_xor_sync(0xffffffffu, s0, 2);
        s1 += __shfl_xor_sync(0xffffffffu, s1, 1);
        s1 += __shfl_xor_sync(0xffffffffu, s1, 2);
        const float inv0 = 1.0f / s0, inv1 = 1.0f / s1;

        #pragma unroll
        for (int j = 0; j < 4; j++) {
            const int col = h*DH + 8*j + 2*gc;
            const size_t r0 = (size_t)(i*NSEQ + jq0 + gr)*CIN + col;
            const size_t r1 = (size_t)(i*NSEQ + jq0 + gr + 8)*CIN + col;
            const float2 g0 = *(const float2*)(g_act + r0);
            const float2 g1 = *(const float2*)(g_act + r1);
            *(float2*)(g_act + r0) = make_float2(o[j][0]*inv0*g0.x, o[j][1]*inv0*g0.y);
            *(float2*)(g_act + r1) = make_float2(o[j][2]*inv1*g1.x, o[j][3]*inv1*g1.y);
        }
    }
}

// ============================================================================
// Kernel 3: out = act @ wo^T + bo  (fp16 mma — unchanged)
// ============================================================================
__global__ __launch_bounds__(256, 2) void k3_out(
    const float* __restrict__ bo, float* __restrict__ out)
{
    extern __shared__ char smc[];
    char* wb[2] = { smc, smc + 64*WSB };

    const int tid  = threadIdx.x;
    const int warp = tid >> 5, lane = tid & 31;
    const int gr   = lane >> 2, gc = lane & 3;
    const int t0   = blockIdx.x * 128;

    #pragma unroll
    for (int s = 0; s < 16; s++) {
        const int idx = tid + 256*s;
        const int lt = idx >> 5, c0 = (idx & 31) * 4;
        const float4 a4 = *(const float4*)(g_act + (size_t)(t0+lt)*CIN + c0);
        char* dst = smc + lt*XSB + c0*2;
        *(__half2*)(dst)     = __floats2half2_rn(a4.x, a4.y);
        *(__half2*)(dst + 4) = __floats2half2_rn(a4.z, a4.w);
    }
    __syncthreads();

    const int m0 = warp * 16;
    uint32_t a[8][4];
    #pragma unroll
    for (int ks = 0; ks < 8; ks++) {
        const char* rp = smc + (m0+gr)*XSB + ks*32 + gc*4;
        a[ks][0] = *(const uint32_t*)(rp);
        a[ks][1] = *(const uint32_t*)(rp + 8*XSB);
        a[ks][2] = *(const uint32_t*)(rp + 16);
        a[ks][3] = *(const uint32_t*)(rp + 8*XSB + 16);
    }
    __syncthreads();

    const uint32_t wbu[2] = { s2u(wb[0]), s2u(wb[1]) };
    #pragma unroll
    for (int q = 0; q < 2; q++) {
        const __half* src = g_wh + 4*16384 + q*8192;
        #pragma unroll
        for (int s = 0; s < 4; s++) {
            const int idx = tid + 256*s;
            const int o = idx >> 4, ch = idx & 15;
            cpa16(wbu[q] + o*WSB + ch*16, src + o*128 + ch*8);
        }
        CPA_COMMIT();
    }

    const int tok = t0 + m0 + gr;
    for (int hf = 0; hf < 2; hf++) {
        if (hf == 0) { CPA_WAIT(1); } else { CPA_WAIT(0); }
        __syncthreads();

        const char* wS = wb[hf];
        float acc[8][4];
        #pragma unroll
        for (int nt = 0; nt < 8; nt++)
            #pragma unroll
            for (int e = 0; e < 4; e++) acc[nt][e] = 0.f;

        #pragma unroll
        for (int ks = 0; ks < 8; ks++) {
            #pragma unroll
            for (int nt = 0; nt < 8; nt++) {
                const uint2 b = *(const uint2*)(wS + (nt*8+gr)*WSB + ks*32 + gc*8);
                mma_f16(acc[nt], a[ks][0], a[ks][1], a[ks][2], a[ks][3], b.x, b.y);
            }
        }

        #pragma unroll
        for (int nt = 0; nt < 8; nt++) {
            const int o = hf*64 + nt*8 + 2*gc;
            const float2 bov = __ldg((const float2*)(bo + o));
            *(float2*)(out + (size_t)tok*CIN + o) =
                make_float2(acc[nt][0]+bov.x, acc[nt][1]+bov.y);
            *(float2*)(out + (size_t)(tok+8)*CIN + o) =
                make_float2(acc[nt][2]+bov.x, acc[nt][3]+bov.y);
        }
    }
}

// ============================================================================
extern "C" void kernel_launch(void* const* d_in, const int* in_sizes, int n_in,
                              void* d_out, int out_size)
{
    const float* x     = (const float*)d_in[0];
    const float* mask  = (const float*)d_in[1];
    const float* gamma = (const float*)d_in[2];
    const float* beta  = (const float*)d_in[3];
    const float* wbias = (const float*)d_in[4];
    const float* wq    = (const float*)d_in[5];
    const float* wk    = (const float*)d_in[6];
    const float* wv    = (const float*)d_in[7];
    const float* wg    = (const float*)d_in[8];
    const float* bg    = (const float*)d_in[9];
    const float* wo    = (const float*)d_in[10];
    const float* bo    = (const float*)d_in[11];
    float* out = (float*)d_out;

    const int smem_gemm = 2 * 64 * WSB;           // 36,864 B

    cudaFuncSetAttribute(k1_ln_proj, cudaFuncAttributeMaxDynamicSharedMemorySize, smem_gemm);
    cudaFuncSetAttribute(k2_attn,   cudaFuncAttributeMaxDynamicSharedMemorySize, K2_SMEM);
    cudaFuncSetAttribute(k3_out,    cudaFuncAttributeMaxDynamicSharedMemorySize, smem_gemm);

    k0_prep  <<<320, 256>>>(wq, wk, wv, wg, wo);
    k1_ln_proj<<<NTOK/128, 256, smem_gemm>>>(x, gamma, beta, wbias, bg);
    k2_attn  <<<NSEQ*NH,  384, K2_SMEM>>>(mask);
    k3_out   <<<NTOK/128, 256, smem_gemm>>>(bo, out);
}